// round 6
// baseline (speedup 1.0000x reference)
#include <cuda_runtime.h>

#define B_DIM 128
#define K_DIM 2048
#define D_DIM 512

#define BM 32            // batch rows per block
#define BN 16            // k cols per block
#define DT 128           // d per pipeline stage
#define NSTAGE 4         // 512 / 128
#define ROWP 132         // floats per smem row (128 + 4 pad) = 528B = 33*16B
#define THREADS 256

// smem: union of stage tiles and reduction buffer, both 67584 bytes.
//   tiles: xs[2][32][132] (33792B) | ps[2][16][132] (16896B) | as[2][16][132]
//   red:   ull R[256][33]
#define XS_OFF 0
#define PS_OFF 33792
#define AS_OFF 50688
#define SMEM_BYTES 67584

typedef unsigned long long ull;

// Scratch for per-row stats (no cudaMalloc allowed)
__device__ float g_uu[K_DIM];   // ||p_k||^2
__device__ float g_ua[K_DIM];   // <u_k, a_k> = -<p_k, a_k>
__device__ float g_a2[K_DIM];   // ||a_k||^2
__device__ float g_vv[B_DIM];   // ||x_b||^2

// ---------------------------------------------------------------------------
// Kernel 1: per-k stats (uu, ua, a2) and per-b stats (vv). One warp per row.
// ---------------------------------------------------------------------------
__global__ void stats_kernel(const float* __restrict__ inp,
                             const float* __restrict__ p,
                             const float* __restrict__ a) {
    int warp = (blockIdx.x * blockDim.x + threadIdx.x) >> 5;
    int lane = threadIdx.x & 31;

    if (warp < K_DIM) {
        const float4* pr = (const float4*)(p + warp * D_DIM);
        const float4* ar = (const float4*)(a + warp * D_DIM);
        float pp = 0.f, pa = 0.f, aa = 0.f;
#pragma unroll
        for (int i = 0; i < D_DIM / 128; i++) {
            float4 pv = pr[lane + i * 32];
            float4 av = ar[lane + i * 32];
            pp += pv.x * pv.x + pv.y * pv.y + pv.z * pv.z + pv.w * pv.w;
            pa += pv.x * av.x + pv.y * av.y + pv.z * av.z + pv.w * av.w;
            aa += av.x * av.x + av.y * av.y + av.z * av.z + av.w * av.w;
        }
#pragma unroll
        for (int off = 16; off > 0; off >>= 1) {
            pp += __shfl_xor_sync(0xFFFFFFFFu, pp, off);
            pa += __shfl_xor_sync(0xFFFFFFFFu, pa, off);
            aa += __shfl_xor_sync(0xFFFFFFFFu, aa, off);
        }
        if (lane == 0) {
            g_uu[warp] = pp;
            g_ua[warp] = -pa;
            g_a2[warp] = aa;
        }
    } else if (warp < K_DIM + B_DIM) {
        int b = warp - K_DIM;
        const float4* xr = (const float4*)(inp + b * D_DIM);
        float vv = 0.f;
#pragma unroll
        for (int i = 0; i < D_DIM / 128; i++) {
            float4 xv = xr[lane + i * 32];
            vv += xv.x * xv.x + xv.y * xv.y + xv.z * xv.z + xv.w * xv.w;
        }
#pragma unroll
        for (int off = 16; off > 0; off >>= 1)
            vv += __shfl_xor_sync(0xFFFFFFFFu, vv, off);
        if (lane == 0) g_vv[b] = vv;
    }
}

// ---------------------------------------------------------------------------
// Packed f32x2 helpers
// ---------------------------------------------------------------------------
__device__ __forceinline__ void fma2(ull& d, ull a, ull b) {
    asm("fma.rn.f32x2 %0, %1, %2, %0;" : "+l"(d) : "l"(a), "l"(b));
}
__device__ __forceinline__ ull add2(ull a, ull b) {
    ull r;
    asm("add.rn.f32x2 %0, %1, %2;" : "=l"(r) : "l"(a), "l"(b));
    return r;
}
__device__ __forceinline__ float fold2(ull v) {      // lo + hi
    return __uint_as_float((unsigned)v) + __uint_as_float((unsigned)(v >> 32));
}

// cp.async helpers
__device__ __forceinline__ void cp16(void* dst, const void* src) {
    unsigned saddr = (unsigned)__cvta_generic_to_shared(dst);
    asm volatile("cp.async.cg.shared.global [%0], [%1], 16;\n"
                 :: "r"(saddr), "l"(src));
}
__device__ __forceinline__ void cp_commit() {
    asm volatile("cp.async.commit_group;\n" ::: "memory");
}
__device__ __forceinline__ void cp_wait1() {
    asm volatile("cp.async.wait_group 1;\n" ::: "memory");
}
__device__ __forceinline__ void cp_wait0() {
    asm volatile("cp.async.wait_group 0;\n" ::: "memory");
}

// ---------------------------------------------------------------------------
// Kernel 2: fused dual GEMM + hyperbolic MLR epilogue.
// Grid (K/16, B/32) = (128,4) = 512 blocks, 256 threads.
// 8-way split-D: warp w handles d-slice [w*16, w*16+16) of each DT=128 stage.
// Per-thread tile 8b x 2k, accumulators packed f32x2 along d (even/odd sums).
// Lane map: b = (l&3) + 4i (i=0..7), k = (l>>2) + 8j (j=0..1)  -> conflict-free.
// ---------------------------------------------------------------------------
__global__ __launch_bounds__(THREADS, 2)
void hyper_logits_kernel(const float* __restrict__ inp,
                         const float* __restrict__ p,
                         const float* __restrict__ a,
                         float* __restrict__ out) {
    __shared__ __align__(16) char sm[SMEM_BYTES];
    float* XS = (float*)(sm + XS_OFF);   // [2][32][ROWP]
    float* PS = (float*)(sm + PS_OFF);   // [2][16][ROWP]
    float* AS = (float*)(sm + AS_OFF);   // [2][16][ROWP]

    const int tid = threadIdx.x;
    const int w = tid >> 5;
    const int l = tid & 31;
    const int bq = l & 3;
    const int kq = l >> 2;
    const int kbase = blockIdx.x * BN;
    const int bbase = blockIdx.y * BM;

    ull accP[8][2] = {};
    ull accA[8][2] = {};

    // ---- stage copy: 2048 float4 (xs 1024, ps 512, as 512); 8 per thread ----
    auto copy_stage = [&](int s, int d0) {
#pragma unroll
        for (int j = 0; j < 4; j++) {
            int id = tid + 256 * j;                 // 0..1023
            int row = id >> 5, c4 = (id & 31) * 4;
            cp16(XS + (s * 32 + row) * ROWP + c4,
                 inp + (bbase + row) * D_DIM + d0 + c4);
        }
#pragma unroll
        for (int j = 0; j < 2; j++) {
            int id = tid + 256 * j;                 // 0..511
            int row = id >> 5, c4 = (id & 31) * 4;
            cp16(PS + (s * 16 + row) * ROWP + c4,
                 p + (kbase + row) * D_DIM + d0 + c4);
        }
#pragma unroll
        for (int j = 0; j < 2; j++) {
            int id = tid + 256 * j;
            int row = id >> 5, c4 = (id & 31) * 4;
            cp16(AS + (s * 16 + row) * ROWP + c4,
                 a + (kbase + row) * D_DIM + d0 + c4);
        }
    };

    copy_stage(0, 0);
    cp_commit();

    for (int t = 0; t < NSTAGE; t++) {
        if (t + 1 < NSTAGE) {
            copy_stage((t + 1) & 1, (t + 1) * DT);
            cp_commit();
            cp_wait1();
        } else {
            cp_wait0();
        }
        __syncthreads();

        const int s = t & 1;
        const float* xb = XS + s * 32 * ROWP;
        const float* pb = PS + s * 16 * ROWP;
        const float* ab = AS + s * 16 * ROWP;

#pragma unroll
        for (int dc = 0; dc < 4; dc++) {
            const int col = w * 16 + dc * 4;        // 4 d's (2 packed pairs)
            ulonglong2 pv0 = *(const ulonglong2*)(pb + kq * ROWP + col);
            ulonglong2 pv1 = *(const ulonglong2*)(pb + (kq + 8) * ROWP + col);
            ulonglong2 av0 = *(const ulonglong2*)(ab + kq * ROWP + col);
            ulonglong2 av1 = *(const ulonglong2*)(ab + (kq + 8) * ROWP + col);
#pragma unroll
            for (int i = 0; i < 8; i++) {
                ulonglong2 xv = *(const ulonglong2*)(xb + (bq + 4 * i) * ROWP + col);
                fma2(accP[i][0], xv.x, pv0.x); fma2(accP[i][0], xv.y, pv0.y);
                fma2(accP[i][1], xv.x, pv1.x); fma2(accP[i][1], xv.y, pv1.y);
                fma2(accA[i][0], xv.x, av0.x); fma2(accA[i][0], xv.y, av0.y);
                fma2(accA[i][1], xv.x, av1.x); fma2(accA[i][1], xv.y, av1.y);
            }
        }
        __syncthreads();
    }

    // ---- cross-warp reduction: repurpose tile smem as ull R[256][33] ----
    ull* R = (ull*)sm;
    {
        ull* Rt = R + tid * 33;
#pragma unroll
        for (int i = 0; i < 8; i++) {
#pragma unroll
            for (int j = 0; j < 2; j++) {
                Rt[2 * i + j]      = accP[i][j];
                Rt[16 + 2 * i + j] = accA[i][j];
            }
        }
    }
    __syncthreads();

    // thread t: lane rl (same lane-coords), b-subindex ri; 2 logits
    const int rl = tid & 31;
    const int ri = tid >> 5;                         // 0..7
    ull sP0 = 0, sP1 = 0, sA0 = 0, sA1 = 0;
#pragma unroll
    for (int ww = 0; ww < 8; ww++) {
        const ull* Rw = R + (ww * 32 + rl) * 33;
        sP0 = add2(sP0, Rw[2 * ri]);
        sP1 = add2(sP1, Rw[2 * ri + 1]);
        sA0 = add2(sA0, Rw[16 + 2 * ri]);
        sA1 = add2(sA1, Rw[16 + 2 * ri + 1]);
    }

    const int b = bbase + (rl & 3) + 4 * ri;
    const float vv = g_vv[b];
    const float xp[2] = {fold2(sP0), fold2(sP1)};
    const float xa[2] = {fold2(sA0), fold2(sA1)};

#pragma unroll
    for (int j = 0; j < 2; j++) {
        const int k = kbase + (rl >> 2) + 8 * j;
        const float uu = g_uu[k];
        const float ua = g_ua[k];
        const float an = sqrtf(g_a2[k]);
        const float lam = 2.0f / (1.0f - uu);
        const float coef = lam * an;
        const float beta = 1.0f - uu;

        float uv = -xp[j];                           // <u,x> = -<p,x>
        float alpha = 1.0f + 2.0f * uv + vv;
        float den   = 1.0f + 2.0f * uv + uu * vv;
        float inv   = 1.0f / den;
        float wa = (alpha * ua + beta * xa[j]) * inv;
        float ww = (alpha * alpha * uu + 2.0f * alpha * beta * uv
                    + beta * beta * vv) * (inv * inv);
        out[b * K_DIM + k] = coef * asinhf(2.0f * wa / (an * (1.0f - ww)));
    }
}

// ---------------------------------------------------------------------------
extern "C" void kernel_launch(void* const* d_in, const int* in_sizes, int n_in,
                              void* d_out, int out_size) {
    const float* inp = (const float*)d_in[0];   // [B, D]
    const float* p   = (const float*)d_in[1];   // [K, D]
    const float* a   = (const float*)d_in[2];   // [K, D]
    float* out = (float*)d_out;                 // [B, K]

    int nwarps = K_DIM + B_DIM;
    int blocks1 = (nwarps * 32 + 255) / 256;
    stats_kernel<<<blocks1, 256>>>(inp, p, a);

    dim3 grid(K_DIM / BN, B_DIM / BM);   // (128, 4) = 512 blocks
    hyper_logits_kernel<<<grid, THREADS>>>(inp, p, a, out);
}

// round 7
// speedup vs baseline: 1.2947x; 1.2947x over previous
#include <cuda_runtime.h>
#include <cuda_bf16.h>
#include <mma.h>

using namespace nvcuda;

#define B_DIM 128
#define K_DIM 2048
#define D_DIM 512

// GEMM tiling
#define BN 16              // k cols per block (grid = K/BN = 128 blocks)
#define DC 64              // d per pipeline stage
#define NSTAGE (D_DIM / DC) // 8
#define PITCH 72           // bf16 elems per smem row (64 + 8 pad) = 144B
#define THREADS 256

// smem layout (bytes), dynamic
#define XH_OFF 0                            // [2][128][PITCH] bf16 = 36864
#define XL_OFF 36864                        // [2][128][PITCH] bf16 = 36864
#define PH_OFF 73728                        // [2][16][PITCH] bf16 = 4608
#define PL_OFF 78336
#define AH_OFF 82944
#define AL_OFF 87552
#define C_OFF  92160                        // 8 warps x 2 mats x 16x16 f32 = 16384
#define SMEM_BYTES 108544

// ---------------------------------------------------------------------------
// Device-global scratch (no cudaMalloc allowed)
// ---------------------------------------------------------------------------
__device__ float g_uu[K_DIM];
__device__ float g_ua[K_DIM];
__device__ float g_a2[K_DIM];
__device__ float g_vv[B_DIM];
__device__ __nv_bfloat16 g_ph[K_DIM * D_DIM];
__device__ __nv_bfloat16 g_pl[K_DIM * D_DIM];
__device__ __nv_bfloat16 g_ah[K_DIM * D_DIM];
__device__ __nv_bfloat16 g_al[K_DIM * D_DIM];
__device__ __nv_bfloat16 g_xh[B_DIM * D_DIM];
__device__ __nv_bfloat16 g_xl[B_DIM * D_DIM];

// 8-byte packed store of 4 bf16
struct __align__(8) bh4 { __nv_bfloat162 a, b; };

__device__ __forceinline__ void split4(float4 v, __nv_bfloat16* hi,
                                       __nv_bfloat16* lo, int idx) {
    __nv_bfloat16 h0 = __float2bfloat16_rn(v.x);
    __nv_bfloat16 h1 = __float2bfloat16_rn(v.y);
    __nv_bfloat16 h2 = __float2bfloat16_rn(v.z);
    __nv_bfloat16 h3 = __float2bfloat16_rn(v.w);
    bh4 H; H.a = __nv_bfloat162(h0, h1); H.b = __nv_bfloat162(h2, h3);
    *(bh4*)(hi + idx) = H;
    bh4 L;
    L.a = __nv_bfloat162(__float2bfloat16_rn(v.x - __bfloat162float(h0)),
                         __float2bfloat16_rn(v.y - __bfloat162float(h1)));
    L.b = __nv_bfloat162(__float2bfloat16_rn(v.z - __bfloat162float(h2)),
                         __float2bfloat16_rn(v.w - __bfloat162float(h3)));
    *(bh4*)(lo + idx) = L;
}

// ---------------------------------------------------------------------------
// Kernel 1: per-row stats (fp32) + bf16 hi/lo split of p, a, x.
// One warp per row: [0,K) -> k rows, [K, K+B) -> b rows.
// ---------------------------------------------------------------------------
__global__ void stats_split_kernel(const float* __restrict__ inp,
                                   const float* __restrict__ p,
                                   const float* __restrict__ a) {
    int warp = (blockIdx.x * blockDim.x + threadIdx.x) >> 5;
    int lane = threadIdx.x & 31;

    if (warp < K_DIM) {
        const float4* pr = (const float4*)(p + warp * D_DIM);
        const float4* ar = (const float4*)(a + warp * D_DIM);
        float pp = 0.f, pa = 0.f, aa = 0.f;
#pragma unroll
        for (int i = 0; i < D_DIM / 128; i++) {
            float4 pv = pr[lane + i * 32];
            float4 av = ar[lane + i * 32];
            pp += pv.x * pv.x + pv.y * pv.y + pv.z * pv.z + pv.w * pv.w;
            pa += pv.x * av.x + pv.y * av.y + pv.z * av.z + pv.w * av.w;
            aa += av.x * av.x + av.y * av.y + av.z * av.z + av.w * av.w;
            int idx = warp * D_DIM + (lane + i * 32) * 4;
            split4(pv, g_ph, g_pl, idx);
            split4(av, g_ah, g_al, idx);
        }
#pragma unroll
        for (int off = 16; off > 0; off >>= 1) {
            pp += __shfl_xor_sync(0xFFFFFFFFu, pp, off);
            pa += __shfl_xor_sync(0xFFFFFFFFu, pa, off);
            aa += __shfl_xor_sync(0xFFFFFFFFu, aa, off);
        }
        if (lane == 0) {
            g_uu[warp] = pp;
            g_ua[warp] = -pa;
            g_a2[warp] = aa;
        }
    } else if (warp < K_DIM + B_DIM) {
        int b = warp - K_DIM;
        const float4* xr = (const float4*)(inp + b * D_DIM);
        float vv = 0.f;
#pragma unroll
        for (int i = 0; i < D_DIM / 128; i++) {
            float4 xv = xr[lane + i * 32];
            vv += xv.x * xv.x + xv.y * xv.y + xv.z * xv.z + xv.w * xv.w;
            split4(xv, g_xh, g_xl, b * D_DIM + (lane + i * 32) * 4);
        }
#pragma unroll
        for (int off = 16; off > 0; off >>= 1)
            vv += __shfl_xor_sync(0xFFFFFFFFu, vv, off);
        if (lane == 0) g_vv[b] = vv;
    }
}

// ---------------------------------------------------------------------------
// cp.async helpers
// ---------------------------------------------------------------------------
__device__ __forceinline__ void cp16(void* dst, const void* src) {
    unsigned saddr = (unsigned)__cvta_generic_to_shared(dst);
    asm volatile("cp.async.cg.shared.global [%0], [%1], 16;\n"
                 :: "r"(saddr), "l"(src));
}
__device__ __forceinline__ void cp_commit() {
    asm volatile("cp.async.commit_group;\n" ::: "memory");
}
__device__ __forceinline__ void cp_wait1() {
    asm volatile("cp.async.wait_group 1;\n" ::: "memory");
}
__device__ __forceinline__ void cp_wait0() {
    asm volatile("cp.async.wait_group 0;\n" ::: "memory");
}

// ---------------------------------------------------------------------------
// Kernel 2: bf16 WMMA dual GEMM (3-term fp32-emulation) + MLR epilogue.
// Grid: K/BN = 128 blocks, 256 threads (8 warps).
// Warp w computes output rows [16w, 16w+16) x 16 k-cols for both GEMMs:
//   xp = xh@ph + xl@ph + xh@pl ;  xa = xh@ah + xl@ah + xh@al
// D pipelined in stages of 64 with 2-deep cp.async double buffering.
// ---------------------------------------------------------------------------
__global__ __launch_bounds__(THREADS, 1)
void hyper_logits_wmma(float* __restrict__ out) {
    extern __shared__ __align__(16) char sm[];
    __nv_bfloat16* XH = (__nv_bfloat16*)(sm + XH_OFF);
    __nv_bfloat16* XL = (__nv_bfloat16*)(sm + XL_OFF);
    __nv_bfloat16* PH = (__nv_bfloat16*)(sm + PH_OFF);
    __nv_bfloat16* PL = (__nv_bfloat16*)(sm + PL_OFF);
    __nv_bfloat16* AH = (__nv_bfloat16*)(sm + AH_OFF);
    __nv_bfloat16* AL = (__nv_bfloat16*)(sm + AL_OFF);
    float* C = (float*)(sm + C_OFF);

    const int tid = threadIdx.x;
    const int warp = tid >> 5;
    const int lane = tid & 31;
    const int kbase = blockIdx.x * BN;

    // ---- stage copy ----
    auto copy_stage = [&](int s, int d0) {
        // X: 128 rows x 64 cols, hi+lo -> 8 cp16/thread
#pragma unroll
        for (int j = 0; j < 4; j++) {
            int id = tid + 256 * j;                 // 0..1023
            int row = id >> 3, c8 = (id & 7) * 8;
            size_t goff = (size_t)row * D_DIM + d0 + c8;
            cp16(XH + (s * 128 + row) * PITCH + c8, g_xh + goff);
            cp16(XL + (s * 128 + row) * PITCH + c8, g_xl + goff);
        }
        // weights: 16 rows x 64 cols x 4 arrays -> 2 cp16/thread
        {
            int half = tid >> 7;                    // 0: p, 1: a
            int r = tid & 127;
            int row = r >> 3, c8 = (r & 7) * 8;
            size_t goff = (size_t)(kbase + row) * D_DIM + d0 + c8;
            int so = (s * 16 + row) * PITCH + c8;
            if (half == 0) {
                cp16(PH + so, g_ph + goff);
                cp16(PL + so, g_pl + goff);
            } else {
                cp16(AH + so, g_ah + goff);
                cp16(AL + so, g_al + goff);
            }
        }
    };

    wmma::fragment<wmma::accumulator, 16, 16, 16, float> fP, fA;
    wmma::fill_fragment(fP, 0.0f);
    wmma::fill_fragment(fA, 0.0f);

    copy_stage(0, 0);
    cp_commit();

    for (int t = 0; t < NSTAGE; t++) {
        if (t + 1 < NSTAGE) {
            copy_stage((t + 1) & 1, (t + 1) * DC);
            cp_commit();
            cp_wait1();
        } else {
            cp_wait0();
        }
        __syncthreads();

        const int s = t & 1;
        const __nv_bfloat16* xh = XH + s * 128 * PITCH + warp * 16 * PITCH;
        const __nv_bfloat16* xl = XL + s * 128 * PITCH + warp * 16 * PITCH;
        const __nv_bfloat16* ph = PH + s * 16 * PITCH;
        const __nv_bfloat16* pl = PL + s * 16 * PITCH;
        const __nv_bfloat16* ah = AH + s * 16 * PITCH;
        const __nv_bfloat16* al = AL + s * 16 * PITCH;

#pragma unroll
        for (int cc = 0; cc < DC / 16; cc++) {
            const int dcol = cc * 16;
            wmma::fragment<wmma::matrix_a, 16, 16, 16, __nv_bfloat16,
                           wmma::row_major> aH, aL;
            wmma::fragment<wmma::matrix_b, 16, 16, 16, __nv_bfloat16,
                           wmma::col_major> bPH, bPL, bAH, bAL;
            wmma::load_matrix_sync(aH, xh + dcol, PITCH);
            wmma::load_matrix_sync(aL, xl + dcol, PITCH);
            wmma::load_matrix_sync(bPH, ph + dcol, PITCH);
            wmma::load_matrix_sync(bPL, pl + dcol, PITCH);
            wmma::load_matrix_sync(bAH, ah + dcol, PITCH);
            wmma::load_matrix_sync(bAL, al + dcol, PITCH);

            wmma::mma_sync(fP, aH, bPH, fP);
            wmma::mma_sync(fP, aL, bPH, fP);
            wmma::mma_sync(fP, aH, bPL, fP);
            wmma::mma_sync(fA, aH, bAH, fA);
            wmma::mma_sync(fA, aL, bAH, fA);
            wmma::mma_sync(fA, aH, bAL, fA);
        }
        __syncthreads();
    }

    // ---- dump accumulators to smem, then scalar epilogue ----
    float* cP = C + warp * 256;
    float* cA = C + 2048 + warp * 256;
    wmma::store_matrix_sync(cP, fP, 16, wmma::mem_row_major);
    wmma::store_matrix_sync(cA, fA, 16, wmma::mem_row_major);
    __syncwarp();

#pragma unroll
    for (int i = 0; i < 8; i++) {
        int idx = lane + 32 * i;                    // 0..255
        int r = idx >> 4;                           // warp-local b row
        int c = idx & 15;                           // local k col
        const int b = warp * 16 + r;
        const int k = kbase + c;

        float xp = cP[idx];
        float xa = cA[idx];

        const float uu = g_uu[k];
        const float ua = g_ua[k];
        const float an = sqrtf(g_a2[k]);
        const float lam = 2.0f / (1.0f - uu);
        const float coef = lam * an;
        const float beta = 1.0f - uu;
        const float vv = g_vv[b];

        float uv = -xp;                             // <u,x> = -<p,x>
        float alpha = 1.0f + 2.0f * uv + vv;
        float den   = 1.0f + 2.0f * uv + uu * vv;
        float inv   = 1.0f / den;
        float wa = (alpha * ua + beta * xa) * inv;
        float ww = (alpha * alpha * uu + 2.0f * alpha * beta * uv
                    + beta * beta * vv) * (inv * inv);
        out[b * K_DIM + k] = coef * asinhf(2.0f * wa / (an * (1.0f - ww)));
    }
}

// ---------------------------------------------------------------------------
extern "C" void kernel_launch(void* const* d_in, const int* in_sizes, int n_in,
                              void* d_out, int out_size) {
    const float* inp = (const float*)d_in[0];   // [B, D]
    const float* p   = (const float*)d_in[1];   // [K, D]
    const float* a   = (const float*)d_in[2];   // [K, D]
    float* out = (float*)d_out;                 // [B, K]

    static bool attr_set = false;
    if (!attr_set) {
        cudaFuncSetAttribute(hyper_logits_wmma,
                             cudaFuncAttributeMaxDynamicSharedMemorySize,
                             SMEM_BYTES);
        attr_set = true;
    }

    int nwarps = K_DIM + B_DIM;
    int blocks1 = (nwarps * 32 + 255) / 256;
    stats_split_kernel<<<blocks1, 256>>>(inp, p, a);

    hyper_logits_wmma<<<K_DIM / BN, THREADS, SMEM_BYTES>>>(out);
}